// round 17
// baseline (speedup 1.0000x reference)
#include <cuda_runtime.h>
#include <cuda_fp16.h>
#include <cstdint>

// ---------------- problem dims ----------------
#define CIN   32
#define COUT  32
#define HIN   512
#define WIN   512
#define HOUT  510
#define WOUT  510
#define NB    16

// ---------------- tiling ----------------
#define TY      4              // output rows per tile (2 row-pairs)
#define TPX     128            // output px per CTA (4 x n32 warp chunks)
#define XPX     130            // staged px (128 + 2 halo)
#define THREADS 256
#define NTILES  4              // y-tiles walked per CTA

// ---------------- smem ----------------
// 64B rows (32 ci fp16), period-8 XOR chunk swizzle -> conflict-free LDSM/STS
#define XSLOT      (XPX * 64)           // 8320
#define RSLOTS     8                    // ring slots (power of 2)
#define W_OFF      (RSLOTS * XSLOT)     // 66560
#define W_BYTES    (288 * 64)           // 18432
#define SMEM_TOTAL (W_OFF + W_BYTES)    // 84992  (2 CTAs/SM)

// pre-packed weights: [kk*32+co][32 ci] fp16, 64B rows (unswizzled in gmem)
__device__ __align__(16) __half w_packed[288 * 32];

__device__ __forceinline__ uint32_t smem_u32(const void* p) {
    uint32_t a;
    asm("{ .reg .u64 t; cvta.to.shared.u64 t, %1; cvt.u32.u64 %0, t; }"
        : "=r"(a) : "l"(p));
    return a;
}
__device__ __forceinline__ uint32_t h2u(__half2 h) {
    return *reinterpret_cast<uint32_t*>(&h);
}
// period-8 swizzle of the 4 16B-chunks within a 64B row
__device__ __forceinline__ int swz2(int r) {
    return (r & 3) ^ ((r >> 2) & 1);
}

#define STS128(addr, a, b, c, d) \
    asm volatile("st.shared.v4.b32 [%0], {%1,%2,%3,%4};" \
        :: "r"(addr), "r"(a), "r"(b), "r"(c), "r"(d) : "memory")

#define LDSM4(r, addr) \
    asm volatile("ldmatrix.sync.aligned.m8n8.x4.shared.b16 {%0,%1,%2,%3}, [%4];" \
        : "=r"((r)[0]), "=r"((r)[1]), "=r"((r)[2]), "=r"((r)[3]) : "r"(addr))

#define MMA_F16(c, a, b0, b1) \
    asm volatile("mma.sync.aligned.m16n8k16.row.col.f32.f16.f16.f32 " \
        "{%0,%1,%2,%3}, {%4,%5,%6,%7}, {%8,%9}, {%0,%1,%2,%3};" \
        : "+f"((c)[0]), "+f"((c)[1]), "+f"((c)[2]), "+f"((c)[3]) \
        : "r"((a)[0]), "r"((a)[1]), "r"((a)[2]), "r"((a)[3]), "r"(b0), "r"(b1))

// =====================================================================
// setup: w (OIHW fp32) -> w_packed [kk*32+co][ci] fp16
// =====================================================================
__global__ void pack_w_kernel(const float* __restrict__ w)
{
    int i = blockIdx.x * 256 + threadIdx.x;
    if (i < 288 * 32) {
        int row = i >> 5;                  // kk*32+co
        int ci  = i & 31;
        int kk  = row >> 5;
        int co  = row & 31;
        w_packed[row * 32 + ci] = __float2half_rn(w[(co * 32 + ci) * 9 + kk]);
    }
}

// =====================================================================
// stage nrows input rows: LDG fp32 -> cvt fp16 -> swizzled ring slots
// =====================================================================
__device__ __forceinline__ void stage_rows(const float* __restrict__ x,
                                           uint32_t sb, int nb, int x0,
                                           int base_row, int nrows, int t)
{
    const int items = nrows * 4 * XPX;       // (j, ci-octet, px)
    #pragma unroll 1
    for (int it = t; it < items; it += THREADS) {
        const int px  = it % XPX;
        const int rem = it / XPX;
        const int o   = rem & 3;
        const int j   = rem >> 2;
        const int yin = base_row + j;
        const int gx  = x0 + px;
        const bool ok = (yin < HIN) && (gx < WIN);
        const float* xp =
            x + ((size_t)(nb * CIN + o * 8) * HIN + yin) * WIN + gx;
        float v[8];
        #pragma unroll
        for (int q = 0; q < 8; ++q)
            v[q] = ok ? xp[(size_t)q * HIN * WIN] : 0.0f;
        __half2 h0 = __floats2half2_rn(v[0], v[1]);
        __half2 h1 = __floats2half2_rn(v[2], v[3]);
        __half2 h2 = __floats2half2_rn(v[4], v[5]);
        __half2 h3 = __floats2half2_rn(v[6], v[7]);
        const uint32_t slot = (uint32_t)((base_row + j) & (RSLOTS - 1));
        STS128(sb + slot * XSLOT + (uint32_t)px * 64
                  + ((uint32_t)(o ^ swz2(px)) << 4),
               h2u(h0), h2u(h1), h2u(h2), h2u(h3));
    }
}

// 8 MMAs: one m32n32 accumulator block vs one (A-ky, B-slot) fragment pair
__device__ __forceinline__ void mma8(float (&cc)[2][4][4],
                                     const uint32_t (&a)[2][4],
                                     const uint32_t (&b)[2][4])
{
    #pragma unroll
    for (int mt = 0; mt < 2; ++mt)
        #pragma unroll
        for (int q = 0; q < 4; ++q)
            MMA_F16(cc[mt][q], a[mt], b[q >> 1][(q & 1) * 2],
                    b[q >> 1][(q & 1) * 2 + 1]);
}

// =====================================================================
// main kernel: 8 warps, m32 x n32 x 2-row fused warp tiles, ring persistent
// =====================================================================
__global__ __launch_bounds__(THREADS, 2)
void conv_mma_kernel(const float* __restrict__ x,
                     const float* __restrict__ bias,
                     float* __restrict__ out)
{
    extern __shared__ char smem[];
    const uint32_t sb = smem_u32(smem);
    const int t    = threadIdx.x;
    const int wid  = t >> 5;
    const int lane = t & 31;

    const int xt = blockIdx.x;            // 0..3
    const int gy = blockIdx.y;            // 0..31
    const int nb = blockIdx.z;            // 0..15
    const int x0 = xt * TPX;
    const int y0 = gy * (NTILES * TY);    // multiple of 16

    // ---- stage W (swizzled 64B rows)
    {
        const uint4* src = reinterpret_cast<const uint4*>(w_packed);
        #pragma unroll 1
        for (int i = t; i < W_BYTES / 16; i += THREADS) {
            uint4 v = src[i];
            const int row = i >> 2;
            const int cch = i & 3;
            STS128(sb + W_OFF + (uint32_t)row * 64
                      + ((uint32_t)(cch ^ swz2(row)) << 4),
                   v.x, v.y, v.z, v.w);
        }
    }

    // ---- prologue: stage rows y0..y0+5
    stage_rows(x, sb, nb, x0, y0, 6, t);
    __syncthreads();

    // lane constants
    const int a_row   = lane & 15;
    const int a_chunk = lane >> 4;
    const int b_n     = (lane & 7) | ((lane >> 4) << 3);
    const int b_chunk = (lane >> 3) & 1;
    const int g  = lane >> 2;
    const int tg = lane & 3;

    const int p    = wid >> 2;            // row-pair 0/1  (rows 2p, 2p+1)
    const int pxwI = wid & 3;             // px chunk 0..3 (n32 each)

    const uint32_t Wb = sb + W_OFF + (uint32_t)a_row * 64;
    const uint32_t aS = (uint32_t)swz2(a_row) << 4;
    uint32_t sS[3];
    #pragma unroll
    for (int kx = 0; kx < 3; ++kx)
        sS[kx] = (uint32_t)swz2(kx + b_n) << 4;     // swz of prow (g2/pxw-free)
    const uint32_t pnOff = (uint32_t)(pxwI * 32 + b_n) * 64;

    float bv[2][2];
    #pragma unroll
    for (int mt = 0; mt < 2; ++mt) {
        bv[mt][0] = __ldg(bias + mt * 16 + g);
        bv[mt][1] = __ldg(bias + mt * 16 + 8 + g);
    }

    #pragma unroll 1
    for (int i = 0; i < NTILES; ++i) {
        const int yin0 = y0 + TY * i;

        // ring bases for the 4 input slots this warp-pair touches
        uint32_t XsB[4];
        #pragma unroll
        for (int d = 0; d < 4; ++d)
            XsB[d] = sb + (uint32_t)((yin0 + 2 * p + d) & (RSLOTS - 1)) * XSLOT
                        + pnOff;

        // accumulators: [dr][mt][q][4]
        float c[2][2][4][4];
        #pragma unroll
        for (int dr = 0; dr < 2; ++dr)
            #pragma unroll
            for (int mt = 0; mt < 2; ++mt)
                #pragma unroll
                for (int q = 0; q < 4; ++q) {
                    c[dr][mt][q][0] = bv[mt][0]; c[dr][mt][q][1] = bv[mt][0];
                    c[dr][mt][q][2] = bv[mt][1]; c[dr][mt][q][3] = bv[mt][1];
                }

        #pragma unroll
        for (int kx = 0; kx < 3; ++kx) {
            #pragma unroll
            for (int kc = 0; kc < 2; ++kc) {
                // cache A for all 3 ky at this (kx,kc)
                uint32_t af[3][2][4];
                const uint32_t aTerm = ((uint32_t)(2 * kc + a_chunk) << 4) ^ aS;
                #pragma unroll
                for (int ky = 0; ky < 3; ++ky)
                    #pragma unroll
                    for (int mt = 0; mt < 2; ++mt)
                        LDSM4(af[ky][mt],
                              Wb + (uint32_t)(((ky * 3 + kx) * 32 + mt * 16) * 64)
                                 + aTerm);

                const uint32_t bTerm =
                    ((uint32_t)(2 * kc + b_chunk) << 4) ^ sS[kx];
                uint32_t bf[2][4];

                // d = 0: consumer (dr=0, ky=0)
                LDSM4(bf[0], XsB[0] + (uint32_t)(kx * 64) + bTerm);
                LDSM4(bf[1], XsB[0] + (uint32_t)(kx * 64) + 1024 + bTerm);
                mma8(c[0], af[0], bf);
                // d = 1: (0,ky1), (1,ky0)
                LDSM4(bf[0], XsB[1] + (uint32_t)(kx * 64) + bTerm);
                LDSM4(bf[1], XsB[1] + (uint32_t)(kx * 64) + 1024 + bTerm);
                mma8(c[0], af[1], bf);
                mma8(c[1], af[0], bf);
                // d = 2: (0,ky2), (1,ky1)
                LDSM4(bf[0], XsB[2] + (uint32_t)(kx * 64) + bTerm);
                LDSM4(bf[1], XsB[2] + (uint32_t)(kx * 64) + 1024 + bTerm);
                mma8(c[0], af[2], bf);
                mma8(c[1], af[1], bf);
                // d = 3: (1,ky2)
                LDSM4(bf[0], XsB[3] + (uint32_t)(kx * 64) + bTerm);
                LDSM4(bf[1], XsB[3] + (uint32_t)(kx * 64) + 1024 + bTerm);
                mma8(c[1], af[2], bf);
            }
        }

        // ---- store both fused rows
        #pragma unroll
        for (int dr = 0; dr < 2; ++dr) {
            const int oy = yin0 + 2 * p + dr;
            if (oy < HOUT) {
                #pragma unroll
                for (int mt = 0; mt < 2; ++mt) {
                    const size_t base0 =
                        ((size_t)(nb * COUT + mt * 16 + g) * HOUT + oy)
                        * (size_t)WOUT;
                    const size_t coStep = (size_t)8 * HOUT * WOUT;
                    #pragma unroll
                    for (int q = 0; q < 4; ++q) {
                        const int ox = x0 + pxwI * 32 + q * 8 + 2 * tg;
                        if (ox < WOUT) {
                            float2 v0 = make_float2(c[dr][mt][q][0],
                                                    c[dr][mt][q][1]);
                            float2 v1 = make_float2(c[dr][mt][q][2],
                                                    c[dr][mt][q][3]);
                            *reinterpret_cast<float2*>(out + base0 + ox) = v0;
                            *reinterpret_cast<float2*>(out + base0 + coStep + ox) = v1;
                        }
                    }
                }
            }
        }

        // ---- stage the 4 rows for tile i+1 (overwrites dead slots)
        if (i + 1 < NTILES) {
            __syncthreads();
            stage_rows(x, sb, nb, x0, yin0 + 6, 4, t);
            __syncthreads();
        }
    }
}

extern "C" void kernel_launch(void* const* d_in, const int* in_sizes, int n_in,
                              void* d_out, int out_size)
{
    const float* x    = (const float*)d_in[0];
    const float* w    = (const float*)d_in[1];
    const float* bias = (const float*)d_in[2];
    float*       out  = (float*)d_out;

    pack_w_kernel<<<36, 256>>>(w);

    cudaFuncSetAttribute(conv_mma_kernel,
                         cudaFuncAttributeMaxDynamicSharedMemorySize, SMEM_TOTAL);

    dim3 grid(4, 32, NB);    // 4 x-tiles, 32 y-walks of 4 tiles, 16 batches
    conv_mma_kernel<<<grid, THREADS, SMEM_TOTAL>>>(x, bias, out);
}